// round 10
// baseline (speedup 1.0000x reference)
#include <cuda_runtime.h>
#include <cstdint>

// Fixed-shape problem: logits [8,19,512,512] f32, target [8,512,512] (int32 on device)
#define NCLS 19
#define HW   262144           // 512*512
#define CHW  (NCLS * HW)
#define NBLK 444              // 3 CTAs per SM
#define NTHR 256

// Per-block partials: [0..18]=prob_sums, [19..37]=intersection, [38..56]=counts,
// [57]=sum w_t*log_pt, [58]=sum alpha*(1-pt)^2*log_pt
__device__ float    g_part[NBLK][64];
__device__ unsigned g_sem;     // zero-initialized; self-resetting

__device__ __forceinline__ float ex2f(float x){ float r; asm("ex2.approx.ftz.f32 %0,%1;":"=f"(r):"f"(x)); return r; }
__device__ __forceinline__ float lg2f(float x){ float r; asm("lg2.approx.ftz.f32 %0,%1;":"=f"(r):"f"(x)); return r; }
__device__ __forceinline__ float rcpf(float x){ float r; asm("rcp.approx.ftz.f32 %0,%1;":"=f"(r):"f"(x)); return r; }

__device__ __forceinline__ uint32_t smem_u32(const void* p) {
    return (uint32_t)__cvta_generic_to_shared(p);
}
__device__ __forceinline__ void cpa4(uint32_t dst, const void* src) {
    asm volatile("cp.async.ca.shared.global [%0], [%1], 4;" :: "r"(dst), "l"(src) : "memory");
}
__device__ __forceinline__ void cpa_commit() {
    asm volatile("cp.async.commit_group;" ::: "memory");
}
__device__ __forceinline__ void cpa_wait1() {
    asm volatile("cp.async.wait_group 1;" ::: "memory");
}

#define L2E 1.44269504088896f
#define LN2 0.69314718055995f

__global__ void __launch_bounds__(NTHR, 3)      // <=85 regs target, 24 warps/SM
fdl_kernel(const float* __restrict__ logits,
           const int*   __restrict__ target,
           const float* __restrict__ cw,
           const float* __restrict__ fa,
           float*       __restrict__ out,
           int P)
{
    __shared__ float s_log[2][NCLS][NTHR];       // 38912 B
    __shared__ int   s_tgt[2][NTHR];             //  2048 B
    __shared__ float s_cw[NCLS], s_fa[NCLS];
    __shared__ float s_red[64];
    __shared__ float s_fin[4][64];
    __shared__ bool  s_last;

    const int tid = threadIdx.x;
    if (tid < NCLS) { s_cw[tid] = cw[tid]; s_fa[tid] = fa[tid]; }
    if (tid < 64)   s_red[tid] = 0.f;
    __syncthreads();

    // Per-thread accumulators
    float ps[NCLS], iq[NCLS];        // iq = 512*count + sum(pt); exact (events <= ~20)
#pragma unroll
    for (int c = 0; c < NCLS; ++c) { ps[c] = 0.f; iq[c] = 0.f; }
    float anll = 0.f, afoc = 0.f;

    const int stride = NBLK * NTHR;  // 113664

    // Per-thread smem slots (each thread only ever touches its own column)
    const uint32_t dL0 = smem_u32(&s_log[0][0][tid]);
    const uint32_t dL1 = smem_u32(&s_log[1][0][tid]);
    const uint32_t dT0 = smem_u32(&s_tgt[0][tid]);
    const uint32_t dT1 = smem_u32(&s_tgt[1][tid]);

    // Issue one iteration's loads into a stage (predicated per-thread; always commit)
#define ISSUE(PIX, DL, DT)                                                     \
    do {                                                                       \
        if ((PIX) < P) {                                                       \
            const int b  = (PIX) >> 18;                                        \
            const int hw = (PIX) & (HW - 1);                                   \
            const float* bp = logits + (size_t)b * CHW + hw;                   \
            _Pragma("unroll")                                                  \
            for (int c = 0; c < NCLS; ++c)                                     \
                cpa4((DL) + (uint32_t)c * (NTHR * 4), bp + (size_t)c * HW);    \
            cpa4((DT), target + (PIX));                                        \
        }                                                                      \
        cpa_commit();                                                          \
    } while (0)

    int pix = blockIdx.x * NTHR + tid;          // < stride <= P always on entry
    ISSUE(pix, dL0, dT0);
    ISSUE(pix + stride, dL1, dT1);

    int stage = 0;
    for (;;) {
        cpa_wait1();                             // oldest group (this stage) complete

        const int tt = stage ? s_tgt[1][tid] : s_tgt[0][tid];

        float e[NCLS];
        float S = 0.f;
#pragma unroll
        for (int c = 0; c < NCLS; ++c) {
            const float v = stage ? s_log[1][c][tid] : s_log[0][c][tid];
            e[c] = ex2f(v * L2E);
            S += e[c];
        }
        float et = e[0];
#pragma unroll
        for (int c = 1; c < NCLS; ++c) et = (tt == c) ? e[c] : et;

        const float invS   = rcpf(S);
        const float pt     = et * invS;
        const float log_pt = lg2f(pt) * LN2;

        anll = fmaf(s_cw[tt], log_pt, anll);
        const float ptf = fmaxf(pt, 1e-8f);
        const float om  = 1.f - ptf;
        afoc = fmaf(s_fa[tt] * om * om, log_pt, afoc);

        const float qadd = pt + 512.f;
#pragma unroll
        for (int c = 0; c < NCLS; ++c) {
            ps[c] = fmaf(e[c], invS, ps[c]);
            iq[c] += (tt == c) ? qadd : 0.f;
        }

        // Refill this stage with the iteration 2 ahead (e[] dead; regs reusable)
        const int pix2 = pix + 2 * stride;
        if (stage) ISSUE(pix2, dL1, dT1); else ISSUE(pix2, dL0, dT0);

        pix += stride;
        if (pix >= P) break;
        stage ^= 1;
    }
#undef ISSUE

    // ---- Block reduction: unpack iq, warp shuffles, smem atomics ----
    const unsigned full = 0xffffffffu;
    const bool lead = ((tid & 31) == 0);
#pragma unroll
    for (int c = 0; c < NCLS; ++c) {
        const float q  = iq[c];
        const float cf = floorf(q * (1.f / 512.f));   // exact count
        float v0 = ps[c], v1 = q - 512.f * cf, v2 = cf;
#pragma unroll
        for (int o = 16; o > 0; o >>= 1) {
            v0 += __shfl_down_sync(full, v0, o);
            v1 += __shfl_down_sync(full, v1, o);
            v2 += __shfl_down_sync(full, v2, o);
        }
        if (lead) {
            atomicAdd(&s_red[c], v0);
            atomicAdd(&s_red[NCLS + c], v1);
            atomicAdd(&s_red[2 * NCLS + c], v2);
        }
    }
    {
        float v0 = anll, v1 = afoc;
#pragma unroll
        for (int o = 16; o > 0; o >>= 1) {
            v0 += __shfl_down_sync(full, v0, o);
            v1 += __shfl_down_sync(full, v1, o);
        }
        if (lead) {
            atomicAdd(&s_red[57], v0);
            atomicAdd(&s_red[58], v1);
        }
    }
    __syncthreads();

    if (tid < 64) g_part[blockIdx.x][tid] = s_red[tid];

    // ---- Last block performs the final reduction (deterministic order) ----
    __threadfence();
    if (tid == 0) s_last = (atomicAdd(&g_sem, 1u) == NBLK - 1);
    __syncthreads();
    if (!s_last) return;

    if (tid == 0) g_sem = 0;    // reset for next graph replay
    __threadfence();

    {
        const int v = tid & 63;
        const int slice = tid >> 6;          // 0..3
        float acc = 0.f;
        for (int bb = slice; bb < NBLK; bb += 4) acc += g_part[bb][v];
        s_fin[slice][v] = acc;
    }
    __syncthreads();
    if (tid < 64)
        s_fin[0][tid] = s_fin[0][tid] + s_fin[1][tid] + s_fin[2][tid] + s_fin[3][tid];
    __syncthreads();

    if (tid == 0) {
        float swt = 0.f;                      // sum w_t from per-class counts
#pragma unroll
        for (int c = 0; c < NCLS; ++c) swt = fmaf(s_fin[0][2 * NCLS + c], s_cw[c], swt);

        const float ce    = -s_fin[0][57] / swt;
        const float focal = -s_fin[0][58] / (float)P;

        float sw = 0.f;
#pragma unroll
        for (int c = 0; c < NCLS; ++c) sw += s_cw[c];
        sw = fmaxf(sw, 1e-8f);

        float dsum = 0.f;
#pragma unroll
        for (int c = 0; c < NCLS; ++c) {
            const float dice = (2.f * s_fin[0][NCLS + c] + 1.f)
                             / (s_fin[0][c] + s_fin[0][2 * NCLS + c] + 1.f);
            dsum += dice * (s_cw[c] / sw);
        }
        const float dice_loss = 1.f - dsum;
        out[0] = 0.4f * ce + 0.3f * focal + 0.3f * dice_loss;
    }
}

extern "C" void kernel_launch(void* const* d_in, const int* in_sizes, int n_in,
                              void* d_out, int out_size)
{
    const float* logits = (const float*)d_in[0];
    const int*   target = (const int*)d_in[1];
    const float* cw     = (const float*)d_in[2];
    const float* fa     = (const float*)d_in[3];
    float*       out    = (float*)d_out;

    const int P = in_sizes[1];   // B*H*W = 2,097,152

    fdl_kernel<<<NBLK, NTHR>>>(logits, target, cw, fa, out, P);
}

// round 11
// speedup vs baseline: 1.0411x; 1.0411x over previous
#include <cuda_runtime.h>

// Fixed-shape problem: logits [8,19,512,512] f32, target [8,512,512] (int32 on device)
#define NCLS 19
#define HW   262144           // 512*512
#define CHW  (NCLS * HW)
#define NBLK 296              // 2 CTAs per SM, exactly resident
#define NTHR 256
#define QMUL 1024.0f          // iq = 1024*count + sum(pt); per-block count < 1024

// Per-block partials: [0..18]=prob_sums, [19..37]=iq packed, [57]=anll, [58]=afoc
__device__ float    g_part[NBLK][64];
__device__ unsigned g_sem;     // zero-initialized; self-resetting

__device__ __forceinline__ float ex2f(float x){ float r; asm("ex2.approx.ftz.f32 %0,%1;":"=f"(r):"f"(x)); return r; }
__device__ __forceinline__ float lg2f(float x){ float r; asm("lg2.approx.ftz.f32 %0,%1;":"=f"(r):"f"(x)); return r; }
__device__ __forceinline__ float rcpf(float x){ float r; asm("rcp.approx.ftz.f32 %0,%1;":"=f"(r):"f"(x)); return r; }

#define L2E 1.44269504088896f
#define LN2 0.69314718055995f

__global__ void __launch_bounds__(NTHR, 2)      // 16 warps/SM; ~90 live regs, no spill
fdl_kernel(const float* __restrict__ logits,
           const int*   __restrict__ target,
           const float* __restrict__ cw,
           const float* __restrict__ fa,
           float*       __restrict__ out,
           int P)
{
    __shared__ float s_cw[NCLS], s_fa[NCLS];
    __shared__ float s_iq[NCLS];                 // per-CTA packed intersection/count
    __shared__ float s_red[64];
    __shared__ float s_fin[4][64];
    __shared__ bool  s_last;

    const int tid = threadIdx.x;
    if (tid < NCLS) { s_cw[tid] = cw[tid]; s_fa[tid] = fa[tid]; s_iq[tid] = 0.f; }
    if (tid < 64)   s_red[tid] = 0.f;
    __syncthreads();

    // Per-thread accumulators
    float ps[NCLS];
#pragma unroll
    for (int c = 0; c < NCLS; ++c) ps[c] = 0.f;
    float anll = 0.f, afoc = 0.f;

    const int stride = NBLK * NTHR;  // 75776

    // ---- Software-pipelined mainloop (prefetch distance 1, default .ca loads) ----
    int pix = blockIdx.x * NTHR + tid;           // always < P on entry
    const float* basep;
    float l[NCLS];
    {
        const int b  = pix >> 18;
        const int hw = pix & (HW - 1);
        basep = logits + (size_t)b * CHW + hw;
#pragma unroll
        for (int c = 0; c < NCLS; ++c) l[c] = __ldg(basep + (size_t)c * HW);
    }
    int tt = __ldg(target + pix);

    for (;;) {
        const int next = pix + stride;

        // Target-class logit: direct load — line is L1-resident (loaded last iter).
        const float ltf = __ldg(basep + (size_t)tt * HW);

        // Consume l[] (frees it for the prefetch)
        float e[NCLS];
        float S = 0.f;
#pragma unroll
        for (int c = 0; c < NCLS; ++c) { e[c] = ex2f(l[c] * L2E); S += e[c]; }

        // Prefetch next iteration (overlaps the remaining compute)
        int tt_next = 0;
        const bool more = (next < P);            // warp-uniform
        if (more) {
            const int b  = next >> 18;
            const int hw = next & (HW - 1);
            basep = logits + (size_t)b * CHW + hw;
#pragma unroll
            for (int c = 0; c < NCLS; ++c) l[c] = __ldg(basep + (size_t)c * HW);
            tt_next = __ldg(target + next);
        }

        const float invS   = rcpf(S);
        const float lg2S   = lg2f(S);
        const float d      = fmaf(ltf, L2E, -lg2S);   // log2(p_t)
        const float log_pt = d * LN2;
        const float pt     = ex2f(d);

        anll = fmaf(s_cw[tt], log_pt, anll);
        const float ptf = fmaxf(pt, 1e-8f);
        const float om  = 1.f - ptf;
        afoc = fmaf(s_fa[tt] * om * om, log_pt, afoc);

        atomicAdd(&s_iq[tt], pt + QMUL);

#pragma unroll
        for (int c = 0; c < NCLS; ++c) ps[c] = fmaf(e[c], invS, ps[c]);

        if (!more) break;
        pix = next;
        tt  = tt_next;
    }

    // ---- Block reduction: ps via shuffles + smem atomics; scalars likewise ----
    const unsigned full = 0xffffffffu;
    const bool lead = ((tid & 31) == 0);
#pragma unroll
    for (int c = 0; c < NCLS; ++c) {
        float v0 = ps[c];
#pragma unroll
        for (int o = 16; o > 0; o >>= 1) v0 += __shfl_down_sync(full, v0, o);
        if (lead) atomicAdd(&s_red[c], v0);
    }
    {
        float v0 = anll, v1 = afoc;
#pragma unroll
        for (int o = 16; o > 0; o >>= 1) {
            v0 += __shfl_down_sync(full, v0, o);
            v1 += __shfl_down_sync(full, v1, o);
        }
        if (lead) {
            atomicAdd(&s_red[57], v0);
            atomicAdd(&s_red[58], v1);
        }
    }
    __syncthreads();

    if (tid < NCLS) s_red[NCLS + tid] = s_iq[tid];   // iq packed -> slots 19..37
    __syncthreads();
    if (tid < 64) g_part[blockIdx.x][tid] = s_red[tid];

    // ---- Last block performs the final reduction (deterministic order) ----
    __threadfence();
    if (tid == 0) s_last = (atomicAdd(&g_sem, 1u) == NBLK - 1);
    __syncthreads();
    if (!s_last) return;

    if (tid == 0) g_sem = 0;    // reset for next graph replay
    __threadfence();

    {
        const int v = tid & 63;
        const int slice = tid >> 6;          // 0..3
        if (v < NCLS || v >= 57) {           // plain sums: ps + scalars
            float acc = 0.f;
            for (int bb = slice; bb < NBLK; bb += 4) acc += g_part[bb][v];
            s_fin[slice][v] = acc;
        } else if (v < 2 * NCLS) {           // iq: unpack PER BLOCK, then sum
            float ai = 0.f, ac = 0.f;
            for (int bb = slice; bb < NBLK; bb += 4) {
                const float q  = g_part[bb][v];
                const float cf = floorf(q * (1.0f / QMUL));   // exact block count
                ai += q - QMUL * cf;
                ac += cf;
            }
            s_fin[slice][v]        = ai;     // intersection -> 19..37
            s_fin[slice][v + NCLS] = ac;     // counts       -> 38..56
        }
    }
    __syncthreads();
    if (tid < 64)
        s_fin[0][tid] = s_fin[0][tid] + s_fin[1][tid] + s_fin[2][tid] + s_fin[3][tid];
    __syncthreads();

    if (tid == 0) {
        float swt = 0.f;                      // sum w_t from per-class counts
#pragma unroll
        for (int c = 0; c < NCLS; ++c) swt = fmaf(s_fin[0][2 * NCLS + c], s_cw[c], swt);

        const float ce    = -s_fin[0][57] / swt;
        const float focal = -s_fin[0][58] / (float)P;

        float sw = 0.f;
#pragma unroll
        for (int c = 0; c < NCLS; ++c) sw += s_cw[c];
        sw = fmaxf(sw, 1e-8f);

        float dsum = 0.f;
#pragma unroll
        for (int c = 0; c < NCLS; ++c) {
            const float dice = (2.f * s_fin[0][NCLS + c] + 1.f)
                             / (s_fin[0][c] + s_fin[0][2 * NCLS + c] + 1.f);
            dsum += dice * (s_cw[c] / sw);
        }
        const float dice_loss = 1.f - dsum;
        out[0] = 0.4f * ce + 0.3f * focal + 0.3f * dice_loss;
    }
}

extern "C" void kernel_launch(void* const* d_in, const int* in_sizes, int n_in,
                              void* d_out, int out_size)
{
    const float* logits = (const float*)d_in[0];
    const int*   target = (const int*)d_in[1];
    const float* cw     = (const float*)d_in[2];
    const float* fa     = (const float*)d_in[3];
    float*       out    = (float*)d_out;

    const int P = in_sizes[1];   // B*H*W = 2,097,152

    fdl_kernel<<<NBLK, NTHR>>>(logits, target, cw, fa, out, P);
}

// round 12
// speedup vs baseline: 1.1397x; 1.0948x over previous
#include <cuda_runtime.h>

// Fixed-shape problem: logits [8,19,512,512] f32, target [8,512,512] (int32 on device)
#define NCLS 19
#define HW   262144           // 512*512
#define CHW  (NCLS * HW)
#define NBLK 444              // 3 CTAs per SM
#define NTHR 256
#define QMUL 1024.0f          // s_iq = 1024*count + sum(pt); per-block count < 1024

// Per-block partials: [0..18]=prob_sums, [19..37]=iq packed, [57]=anll, [58]=afoc
__device__ float    g_part[NBLK][64];
__device__ unsigned g_sem;     // zero-initialized; self-resetting

__device__ __forceinline__ float ex2f(float x){ float r; asm("ex2.approx.ftz.f32 %0,%1;":"=f"(r):"f"(x)); return r; }
__device__ __forceinline__ float lg2f(float x){ float r; asm("lg2.approx.ftz.f32 %0,%1;":"=f"(r):"f"(x)); return r; }
__device__ __forceinline__ float rcpf(float x){ float r; asm("rcp.approx.ftz.f32 %0,%1;":"=f"(r):"f"(x)); return r; }
__device__ __forceinline__ void  pfL2(const void* p){ asm volatile("prefetch.global.L2 [%0];" :: "l"(p)); }

#define L2E 1.44269504088896f
#define LN2 0.69314718055995f

__global__ void __launch_bounds__(NTHR, 3)      // 24 warps/SM, <=85 regs
fdl_kernel(const float* __restrict__ logits,
           const int*   __restrict__ target,
           const float* __restrict__ cw,
           const float* __restrict__ fa,
           float*       __restrict__ out,
           int P)
{
    __shared__ float s_cw[NCLS], s_fa[NCLS];
    __shared__ float s_iq[NCLS];                 // per-CTA packed intersection/count
    __shared__ float s_red[64];
    __shared__ float s_fin[4][64];
    __shared__ bool  s_last;

    const int tid = threadIdx.x;
    if (tid < NCLS) { s_cw[tid] = cw[tid]; s_fa[tid] = fa[tid]; s_iq[tid] = 0.f; }
    if (tid < 64)   s_red[tid] = 0.f;
    __syncthreads();

    float ps[NCLS];
#pragma unroll
    for (int c = 0; c < NCLS; ++c) ps[c] = 0.f;
    float anll = 0.f, afoc = 0.f;

    const int  stride = NBLK * NTHR;             // 113664
    const bool lane0  = ((tid & 31) == 0);

    // ---- Software-pipelined mainloop:
    //   LDG for iter k+1 issued during compute of k (distance 1),
    //   prefetch.L2 for iter k+2 (distance 2, lane 0 only, 1 line/warp/class).
    int pix = blockIdx.x * NTHR + tid;           // always < P on entry
    const float* basep;
    float l[NCLS];
    {
        const int b  = pix >> 18;
        const int hw = pix & (HW - 1);
        basep = logits + (size_t)b * CHW + hw;
#pragma unroll
        for (int c = 0; c < NCLS; ++c) l[c] = __ldg(basep + (size_t)c * HW);
    }
    int tt = __ldg(target + pix);
    {   // warm L2 for iteration 1
        const int p1 = pix + stride;
        if (lane0 && p1 < P) {
            const int b  = p1 >> 18;
            const int hw = p1 & (HW - 1);
            const float* bp = logits + (size_t)b * CHW + hw;
#pragma unroll
            for (int c = 0; c < NCLS; ++c) pfL2(bp + (size_t)c * HW);
            pfL2(target + p1);
        }
    }

    for (;;) {
        const int next = pix + stride;

        // Target-class logit: one L1-resident gather (lines loaded last step)
        const float ltf = __ldg(basep + (size_t)tt * HW);

        // Consume l[] (frees registers for the prefetch)
        float e[NCLS];
        float S = 0.f;
#pragma unroll
        for (int c = 0; c < NCLS; ++c) { e[c] = ex2f(l[c] * L2E); S += e[c]; }

        // Distance-2 L2 prefetch (no registers, no dependencies)
        {
            const int p2 = pix + 2 * stride;
            if (lane0 && p2 < P) {
                const int b  = p2 >> 18;
                const int hw = p2 & (HW - 1);
                const float* bp = logits + (size_t)b * CHW + hw;
#pragma unroll
                for (int c = 0; c < NCLS; ++c) pfL2(bp + (size_t)c * HW);
                pfL2(target + p2);
            }
        }

        // Distance-1 loads (should now hit L2)
        int tt_next = 0;
        const bool more = (next < P);            // warp-uniform
        if (more) {
            const int b  = next >> 18;
            const int hw = next & (HW - 1);
            basep = logits + (size_t)b * CHW + hw;
#pragma unroll
            for (int c = 0; c < NCLS; ++c) l[c] = __ldg(basep + (size_t)c * HW);
            tt_next = __ldg(target + next);
        }

        const float invS   = rcpf(S);
        const float d      = fmaf(ltf, L2E, -lg2f(S));   // log2(p_t)
        const float log_pt = d * LN2;
        const float pt     = ex2f(d);

        anll = fmaf(s_cw[tt], log_pt, anll);
        const float ptf = fmaxf(pt, 1e-8f);
        const float om  = 1.f - ptf;
        afoc = fmaf(s_fa[tt] * om * om, log_pt, afoc);

        atomicAdd(&s_iq[tt], pt + QMUL);

#pragma unroll
        for (int c = 0; c < NCLS; ++c) ps[c] = fmaf(e[c], invS, ps[c]);

        if (!more) break;
        pix = next;
        tt  = tt_next;
    }

    // ---- Block reduction ----
    const unsigned full = 0xffffffffu;
    const bool lead = ((tid & 31) == 0);
#pragma unroll
    for (int c = 0; c < NCLS; ++c) {
        float v0 = ps[c];
#pragma unroll
        for (int o = 16; o > 0; o >>= 1) v0 += __shfl_down_sync(full, v0, o);
        if (lead) atomicAdd(&s_red[c], v0);
    }
    {
        float v0 = anll, v1 = afoc;
#pragma unroll
        for (int o = 16; o > 0; o >>= 1) {
            v0 += __shfl_down_sync(full, v0, o);
            v1 += __shfl_down_sync(full, v1, o);
        }
        if (lead) {
            atomicAdd(&s_red[57], v0);
            atomicAdd(&s_red[58], v1);
        }
    }
    __syncthreads();

    if (tid < NCLS) s_red[NCLS + tid] = s_iq[tid];   // iq packed -> slots 19..37
    __syncthreads();
    if (tid < 64) g_part[blockIdx.x][tid] = s_red[tid];

    // ---- Last block performs the final reduction (deterministic order) ----
    __threadfence();
    if (tid == 0) s_last = (atomicAdd(&g_sem, 1u) == NBLK - 1);
    __syncthreads();
    if (!s_last) return;

    if (tid == 0) g_sem = 0;    // reset for next graph replay
    __threadfence();

    {
        const int v = tid & 63;
        const int slice = tid >> 6;          // 0..3
        if (v < NCLS || v >= 57) {           // plain sums: ps + scalars
            float acc = 0.f;
            for (int bb = slice; bb < NBLK; bb += 4) acc += g_part[bb][v];
            s_fin[slice][v] = acc;
        } else if (v < 2 * NCLS) {           // iq: unpack PER BLOCK, then sum
            float ai = 0.f, ac = 0.f;
            for (int bb = slice; bb < NBLK; bb += 4) {
                const float q  = g_part[bb][v];
                const float cf = floorf(q * (1.0f / QMUL));   // exact block count
                ai += q - QMUL * cf;
                ac += cf;
            }
            s_fin[slice][v]        = ai;     // intersection -> 19..37
            s_fin[slice][v + NCLS] = ac;     // counts       -> 38..56
        }
    }
    __syncthreads();
    if (tid < 64)
        s_fin[0][tid] = s_fin[0][tid] + s_fin[1][tid] + s_fin[2][tid] + s_fin[3][tid];
    __syncthreads();

    if (tid == 0) {
        float swt = 0.f;                      // sum w_t from per-class counts
#pragma unroll
        for (int c = 0; c < NCLS; ++c) swt = fmaf(s_fin[0][2 * NCLS + c], s_cw[c], swt);

        const float ce    = -s_fin[0][57] / swt;
        const float focal = -s_fin[0][58] / (float)P;

        float sw = 0.f;
#pragma unroll
        for (int c = 0; c < NCLS; ++c) sw += s_cw[c];
        sw = fmaxf(sw, 1e-8f);

        float dsum = 0.f;
#pragma unroll
        for (int c = 0; c < NCLS; ++c) {
            const float dice = (2.f * s_fin[0][NCLS + c] + 1.f)
                             / (s_fin[0][c] + s_fin[0][2 * NCLS + c] + 1.f);
            dsum += dice * (s_cw[c] / sw);
        }
        const float dice_loss = 1.f - dsum;
        out[0] = 0.4f * ce + 0.3f * focal + 0.3f * dice_loss;
    }
}

extern "C" void kernel_launch(void* const* d_in, const int* in_sizes, int n_in,
                              void* d_out, int out_size)
{
    const float* logits = (const float*)d_in[0];
    const int*   target = (const int*)d_in[1];
    const float* cw     = (const float*)d_in[2];
    const float* fa     = (const float*)d_in[3];
    float*       out    = (float*)d_out;

    const int P = in_sizes[1];   // B*H*W = 2,097,152

    fdl_kernel<<<NBLK, NTHR>>>(logits, target, cw, fa, out, P);
}

// round 13
// speedup vs baseline: 1.1405x; 1.0007x over previous
#include <cuda_runtime.h>

// Fixed-shape problem: logits [8,19,512,512] f32, target [8,512,512] (int32 on device)
#define NCLS 19
#define HW   262144           // 512*512
#define CHW  (NCLS * HW)
#define NBLK 444              // 3 CTAs per SM
#define NTHR 256
#define QMUL 1024.0f          // s_iq = 1024*count + sum(pt); per-block count < 1024

// Per-block partials: [0..18]=prob_sums, [19..37]=iq packed, [57]=anll, [58]=afoc
__device__ float    g_part[NBLK][64];
__device__ unsigned g_sem;     // zero-initialized; self-resetting

__device__ __forceinline__ float ex2f(float x){ float r; asm("ex2.approx.ftz.f32 %0,%1;":"=f"(r):"f"(x)); return r; }
__device__ __forceinline__ float lg2f(float x){ float r; asm("lg2.approx.ftz.f32 %0,%1;":"=f"(r):"f"(x)); return r; }
__device__ __forceinline__ float rcpf(float x){ float r; asm("rcp.approx.ftz.f32 %0,%1;":"=f"(r):"f"(x)); return r; }
__device__ __forceinline__ void  pfL2(const void* p){ asm volatile("prefetch.global.L2 [%0];" :: "l"(p)); }

#define L2E 1.44269504088896f
#define LN2 0.69314718055995f

__global__ void __launch_bounds__(NTHR, 3)      // 24 warps/SM, <=85 regs
fdl_kernel(const float* __restrict__ logits,
           const int*   __restrict__ target,
           const float* __restrict__ cw,
           const float* __restrict__ fa,
           float*       __restrict__ out,
           int P)
{
    __shared__ float s_cw[NCLS], s_fa[NCLS];
    __shared__ float s_iq[NCLS];                 // per-CTA packed intersection/count
    __shared__ float s_red[64];
    __shared__ float s_fin[4][64];
    __shared__ bool  s_last;

    const int tid = threadIdx.x;
    if (tid < NCLS) { s_cw[tid] = cw[tid]; s_fa[tid] = fa[tid]; s_iq[tid] = 0.f; }
    if (tid < 64)   s_red[tid] = 0.f;
    __syncthreads();

    float ps[NCLS];
#pragma unroll
    for (int c = 0; c < NCLS; ++c) ps[c] = 0.f;
    float anll = 0.f, afoc = 0.f;

    const int  stride = NBLK * NTHR;             // 113664
    const bool lane0  = ((tid & 31) == 0);

    // ---- Software-pipelined mainloop:
    //   LDG for iter k+1 issued during compute of k (distance 1, lands in L2-hit),
    //   prefetch.L2 for iter k+2 (distance 2, lane 0 only, 1 line/warp/class).
    int pix = blockIdx.x * NTHR + tid;           // always < P on entry
    float l[NCLS];
    {
        const int b  = pix >> 18;
        const int hw = pix & (HW - 1);
        const float* bp = logits + (size_t)b * CHW + hw;
#pragma unroll
        for (int c = 0; c < NCLS; ++c) l[c] = __ldg(bp + (size_t)c * HW);
    }
    int tt = __ldg(target + pix);
    {   // warm L2 for iteration 1
        const int p1 = pix + stride;
        if (lane0 && p1 < P) {
            const int b  = p1 >> 18;
            const int hw = p1 & (HW - 1);
            const float* bp = logits + (size_t)b * CHW + hw;
#pragma unroll
            for (int c = 0; c < NCLS; ++c) pfL2(bp + (size_t)c * HW);
            pfL2(target + p1);
        }
    }

    for (;;) {
        const int next = pix + stride;

        // Target-class logit via select chain over l[] (alu pipe — has headroom;
        // avoids the scattered L1 gather that cost ~14 wavefronts/warp-iter)
        float yt = l[0];
#pragma unroll
        for (int c = 1; c < NCLS; ++c) yt = (tt == c) ? l[c] : yt;

        // Consume l[] (frees registers for the next-iteration loads)
        float e[NCLS];
        float S = 0.f;
#pragma unroll
        for (int c = 0; c < NCLS; ++c) { e[c] = ex2f(l[c] * L2E); S += e[c]; }

        // Distance-2 L2 prefetch (no registers, no dependencies)
        {
            const int p2 = pix + 2 * stride;
            if (lane0 && p2 < P) {
                const int b  = p2 >> 18;
                const int hw = p2 & (HW - 1);
                const float* bp = logits + (size_t)b * CHW + hw;
#pragma unroll
                for (int c = 0; c < NCLS; ++c) pfL2(bp + (size_t)c * HW);
                pfL2(target + p2);
            }
        }

        // Distance-1 loads (L2 hits thanks to the prefetch)
        int tt_next = 0;
        const bool more = (next < P);            // warp-uniform
        if (more) {
            const int b  = next >> 18;
            const int hw = next & (HW - 1);
            const float* bp = logits + (size_t)b * CHW + hw;
#pragma unroll
            for (int c = 0; c < NCLS; ++c) l[c] = __ldg(bp + (size_t)c * HW);
            tt_next = __ldg(target + next);
        }

        const float invS   = rcpf(S);
        const float d      = fmaf(yt, L2E, -lg2f(S));   // log2(p_t)
        const float log_pt = d * LN2;
        const float pt     = ex2f(d);

        anll = fmaf(s_cw[tt], log_pt, anll);
        const float ptf = fmaxf(pt, 1e-8f);
        const float om  = 1.f - ptf;
        afoc = fmaf(s_fa[tt] * om * om, log_pt, afoc);

        atomicAdd(&s_iq[tt], pt + QMUL);

#pragma unroll
        for (int c = 0; c < NCLS; ++c) ps[c] = fmaf(e[c], invS, ps[c]);

        if (!more) break;
        pix = next;
        tt  = tt_next;
    }

    // ---- Block reduction ----
    const unsigned full = 0xffffffffu;
    const bool lead = ((tid & 31) == 0);
#pragma unroll
    for (int c = 0; c < NCLS; ++c) {
        float v0 = ps[c];
#pragma unroll
        for (int o = 16; o > 0; o >>= 1) v0 += __shfl_down_sync(full, v0, o);
        if (lead) atomicAdd(&s_red[c], v0);
    }
    {
        float v0 = anll, v1 = afoc;
#pragma unroll
        for (int o = 16; o > 0; o >>= 1) {
            v0 += __shfl_down_sync(full, v0, o);
            v1 += __shfl_down_sync(full, v1, o);
        }
        if (lead) {
            atomicAdd(&s_red[57], v0);
            atomicAdd(&s_red[58], v1);
        }
    }
    __syncthreads();

    if (tid < NCLS) s_red[NCLS + tid] = s_iq[tid];   // iq packed -> slots 19..37
    __syncthreads();
    if (tid < 64) g_part[blockIdx.x][tid] = s_red[tid];

    // ---- Last block performs the final reduction (deterministic order) ----
    __threadfence();
    if (tid == 0) s_last = (atomicAdd(&g_sem, 1u) == NBLK - 1);
    __syncthreads();
    if (!s_last) return;

    if (tid == 0) g_sem = 0;    // reset for next graph replay
    __threadfence();

    {
        const int v = tid & 63;
        const int slice = tid >> 6;          // 0..3
        if (v < NCLS || v >= 57) {           // plain sums: ps + scalars
            float acc = 0.f;
            for (int bb = slice; bb < NBLK; bb += 4) acc += g_part[bb][v];
            s_fin[slice][v] = acc;
        } else if (v < 2 * NCLS) {           // iq: unpack PER BLOCK, then sum
            float ai = 0.f, ac = 0.f;
            for (int bb = slice; bb < NBLK; bb += 4) {
                const float q  = g_part[bb][v];
                const float cf = floorf(q * (1.0f / QMUL));   // exact block count
                ai += q - QMUL * cf;
                ac += cf;
            }
            s_fin[slice][v]        = ai;     // intersection -> 19..37
            s_fin[slice][v + NCLS] = ac;     // counts       -> 38..56
        }
    }
    __syncthreads();
    if (tid < 64)
        s_fin[0][tid] = s_fin[0][tid] + s_fin[1][tid] + s_fin[2][tid] + s_fin[3][tid];
    __syncthreads();

    if (tid == 0) {
        float swt = 0.f;                      // sum w_t from per-class counts
#pragma unroll
        for (int c = 0; c < NCLS; ++c) swt = fmaf(s_fin[0][2 * NCLS + c], s_cw[c], swt);

        const float ce    = -s_fin[0][57] / swt;
        const float focal = -s_fin[0][58] / (float)P;

        float sw = 0.f;
#pragma unroll
        for (int c = 0; c < NCLS; ++c) sw += s_cw[c];
        sw = fmaxf(sw, 1e-8f);

        float dsum = 0.f;
#pragma unroll
        for (int c = 0; c < NCLS; ++c) {
            const float dice = (2.f * s_fin[0][NCLS + c] + 1.f)
                             / (s_fin[0][c] + s_fin[0][2 * NCLS + c] + 1.f);
            dsum += dice * (s_cw[c] / sw);
        }
        const float dice_loss = 1.f - dsum;
        out[0] = 0.4f * ce + 0.3f * focal + 0.3f * dice_loss;
    }
}

extern "C" void kernel_launch(void* const* d_in, const int* in_sizes, int n_in,
                              void* d_out, int out_size)
{
    const float* logits = (const float*)d_in[0];
    const int*   target = (const int*)d_in[1];
    const float* cw     = (const float*)d_in[2];
    const float* fa     = (const float*)d_in[3];
    float*       out    = (float*)d_out;

    const int P = in_sizes[1];   // B*H*W = 2,097,152

    fdl_kernel<<<NBLK, NTHR>>>(logits, target, cw, fa, out, P);
}

// round 14
// speedup vs baseline: 1.1761x; 1.0312x over previous
#include <cuda_runtime.h>

// Fixed-shape problem: logits [8,19,512,512] f32, target [8,512,512] (int32 on device)
#define NCLS 19
#define HW   262144           // 512*512
#define HW2  131072           // float2 pairs per plane
#define CHW  (NCLS * HW)
#define NBLK 296              // 2 CTAs per SM
#define NTHR 256
#define QMUL 1024.0f          // s_iq = 1024*count + sum(pt); per-block count < 1024

// Per-block partials: [0..18]=prob_sums, [19..37]=iq packed, [57]=anll, [58]=afoc
__device__ float    g_part[NBLK][64];
__device__ unsigned g_sem;     // zero-initialized; self-resetting

__device__ __forceinline__ float ex2f(float x){ float r; asm("ex2.approx.ftz.f32 %0,%1;":"=f"(r):"f"(x)); return r; }
__device__ __forceinline__ float lg2f(float x){ float r; asm("lg2.approx.ftz.f32 %0,%1;":"=f"(r):"f"(x)); return r; }
__device__ __forceinline__ float rcpf(float x){ float r; asm("rcp.approx.ftz.f32 %0,%1;":"=f"(r):"f"(x)); return r; }
__device__ __forceinline__ void  pfL2(const void* p){ asm volatile("prefetch.global.L2 [%0];" :: "l"(p)); }

#define L2E 1.44269504088896f
#define LN2 0.69314718055995f

__global__ void __launch_bounds__(NTHR, 2)      // 16 warps/SM, 128-reg cap, ~85 live
fdl_kernel(const float* __restrict__ logits,
           const int*   __restrict__ target,
           const float* __restrict__ cw,
           const float* __restrict__ fa,
           float*       __restrict__ out,
           int P2)
{
    __shared__ float s_cw[NCLS], s_fa[NCLS];
    __shared__ float s_iq[NCLS];                 // per-CTA packed intersection/count
    __shared__ float s_red[64];
    __shared__ float s_fin[4][64];
    __shared__ bool  s_last;

    const int tid = threadIdx.x;
    if (tid < NCLS) { s_cw[tid] = cw[tid]; s_fa[tid] = fa[tid]; s_iq[tid] = 0.f; }
    if (tid < 64)   s_red[tid] = 0.f;
    __syncthreads();

    float ps[NCLS];
#pragma unroll
    for (int c = 0; c < NCLS; ++c) ps[c] = 0.f;
    float anll = 0.f, afoc = 0.f;

    const int  stride = NBLK * NTHR;             // 75776 pixel-pairs
    const bool pflane = ((tid & 15) == 0);       // lanes 0 and 16: one 128B line each

    // ---- Pipeline: d1 register loads (float2), d2 L2 prefetch ----
    int pp = blockIdx.x * NTHR + tid;            // pixel-pair index; < P2 on entry
    const float2* basep;
    float2 l[NCLS];
    {
        const int b  = pp >> 17;
        const int hw = pp & (HW2 - 1);
        basep = (const float2*)(logits + (size_t)b * CHW) + hw;
#pragma unroll
        for (int c = 0; c < NCLS; ++c) l[c] = __ldg(basep + (size_t)c * HW2);
    }
    int2 t2 = __ldg((const int2*)target + pp);
    {   // warm L2 for iteration 1
        const int p1 = pp + stride;
        if (pflane && p1 < P2) {
            const int b  = p1 >> 17;
            const int hw = p1 & (HW2 - 1);
            const float2* bp = (const float2*)(logits + (size_t)b * CHW) + hw;
#pragma unroll
            for (int c = 0; c < NCLS; ++c) pfL2(bp + (size_t)c * HW2);
            pfL2((const int2*)target + p1);
        }
    }

    for (;;) {
        const int next = pp + stride;

        // Target-class logits: two L1-resident gathers (lines loaded last step)
        const float2 lt0 = __ldg(basep + (size_t)t2.x * HW2);
        const float2 lt1 = __ldg(basep + (size_t)t2.y * HW2);
        const float yt0 = lt0.x;
        const float yt1 = lt1.y;
        const int   tt0 = t2.x, tt1 = t2.y;

        // Consume l[] (frees registers for the next-iteration loads)
        float ex[NCLS], ey[NCLS];
        float Sx = 0.f, Sy = 0.f;
#pragma unroll
        for (int c = 0; c < NCLS; ++c) {
            ex[c] = ex2f(l[c].x * L2E);  Sx += ex[c];
            ey[c] = ex2f(l[c].y * L2E);  Sy += ey[c];
        }

        // Distance-2 L2 prefetch (no registers, no dependencies)
        {
            const int p2i = pp + 2 * stride;
            if (pflane && p2i < P2) {
                const int b  = p2i >> 17;
                const int hw = p2i & (HW2 - 1);
                const float2* bp = (const float2*)(logits + (size_t)b * CHW) + hw;
#pragma unroll
                for (int c = 0; c < NCLS; ++c) pfL2(bp + (size_t)c * HW2);
                pfL2((const int2*)target + p2i);
            }
        }

        // Distance-1 loads (L2 hits thanks to the prefetch)
        int2 t2n = make_int2(0, 0);
        const bool more = (next < P2);           // warp-uniform
        if (more) {
            const int b  = next >> 17;
            const int hw = next & (HW2 - 1);
            basep = (const float2*)(logits + (size_t)b * CHW) + hw;
#pragma unroll
            for (int c = 0; c < NCLS; ++c) l[c] = __ldg(basep + (size_t)c * HW2);
            t2n = __ldg((const int2*)target + next);
        }

        const float invSx = rcpf(Sx);
        const float invSy = rcpf(Sy);

        // Pixel 0
        {
            const float d      = fmaf(yt0, L2E, -lg2f(Sx));
            const float log_pt = d * LN2;
            const float pt     = ex2f(d);
            anll = fmaf(s_cw[tt0], log_pt, anll);
            const float om = 1.f - fmaxf(pt, 1e-8f);
            afoc = fmaf(s_fa[tt0] * om * om, log_pt, afoc);
            atomicAdd(&s_iq[tt0], pt + QMUL);
        }
        // Pixel 1
        {
            const float d      = fmaf(yt1, L2E, -lg2f(Sy));
            const float log_pt = d * LN2;
            const float pt     = ex2f(d);
            anll = fmaf(s_cw[tt1], log_pt, anll);
            const float om = 1.f - fmaxf(pt, 1e-8f);
            afoc = fmaf(s_fa[tt1] * om * om, log_pt, afoc);
            atomicAdd(&s_iq[tt1], pt + QMUL);
        }

#pragma unroll
        for (int c = 0; c < NCLS; ++c)
            ps[c] = fmaf(ex[c], invSx, fmaf(ey[c], invSy, ps[c]));

        if (!more) break;
        pp = next;
        t2 = t2n;
    }

    // ---- Block reduction ----
    const unsigned full = 0xffffffffu;
    const bool lead = ((tid & 31) == 0);
#pragma unroll
    for (int c = 0; c < NCLS; ++c) {
        float v0 = ps[c];
#pragma unroll
        for (int o = 16; o > 0; o >>= 1) v0 += __shfl_down_sync(full, v0, o);
        if (lead) atomicAdd(&s_red[c], v0);
    }
    {
        float v0 = anll, v1 = afoc;
#pragma unroll
        for (int o = 16; o > 0; o >>= 1) {
            v0 += __shfl_down_sync(full, v0, o);
            v1 += __shfl_down_sync(full, v1, o);
        }
        if (lead) {
            atomicAdd(&s_red[57], v0);
            atomicAdd(&s_red[58], v1);
        }
    }
    __syncthreads();

    if (tid < NCLS) s_red[NCLS + tid] = s_iq[tid];   // iq packed -> slots 19..37
    __syncthreads();
    if (tid < 64) g_part[blockIdx.x][tid] = s_red[tid];

    // ---- Last block performs the final reduction (deterministic order) ----
    __threadfence();
    if (tid == 0) s_last = (atomicAdd(&g_sem, 1u) == NBLK - 1);
    __syncthreads();
    if (!s_last) return;

    if (tid == 0) g_sem = 0;    // reset for next graph replay
    __threadfence();

    {
        const int v = tid & 63;
        const int slice = tid >> 6;          // 0..3
        if (v < NCLS || v >= 57) {           // plain sums: ps + scalars
            float acc = 0.f;
            for (int bb = slice; bb < NBLK; bb += 4) acc += g_part[bb][v];
            s_fin[slice][v] = acc;
        } else if (v < 2 * NCLS) {           // iq: unpack PER BLOCK, then sum
            float ai = 0.f, ac = 0.f;
            for (int bb = slice; bb < NBLK; bb += 4) {
                const float q  = g_part[bb][v];
                const float cf = floorf(q * (1.0f / QMUL));   // exact block count
                ai += q - QMUL * cf;
                ac += cf;
            }
            s_fin[slice][v]        = ai;     // intersection -> 19..37
            s_fin[slice][v + NCLS] = ac;     // counts       -> 38..56
        }
    }
    __syncthreads();
    if (tid < 64)
        s_fin[0][tid] = s_fin[0][tid] + s_fin[1][tid] + s_fin[2][tid] + s_fin[3][tid];
    __syncthreads();

    if (tid == 0) {
        const float Pf = (float)P2 * 2.0f;
        float swt = 0.f;                      // sum w_t from per-class counts
#pragma unroll
        for (int c = 0; c < NCLS; ++c) swt = fmaf(s_fin[0][2 * NCLS + c], s_cw[c], swt);

        const float ce    = -s_fin[0][57] / swt;
        const float focal = -s_fin[0][58] / Pf;

        float sw = 0.f;
#pragma unroll
        for (int c = 0; c < NCLS; ++c) sw += s_cw[c];
        sw = fmaxf(sw, 1e-8f);

        float dsum = 0.f;
#pragma unroll
        for (int c = 0; c < NCLS; ++c) {
            const float dice = (2.f * s_fin[0][NCLS + c] + 1.f)
                             / (s_fin[0][c] + s_fin[0][2 * NCLS + c] + 1.f);
            dsum += dice * (s_cw[c] / sw);
        }
        const float dice_loss = 1.f - dsum;
        out[0] = 0.4f * ce + 0.3f * focal + 0.3f * dice_loss;
    }
}

extern "C" void kernel_launch(void* const* d_in, const int* in_sizes, int n_in,
                              void* d_out, int out_size)
{
    const float* logits = (const float*)d_in[0];
    const int*   target = (const int*)d_in[1];
    const float* cw     = (const float*)d_in[2];
    const float* fa     = (const float*)d_in[3];
    float*       out    = (float*)d_out;

    const int P2 = in_sizes[1] / 2;   // 1,048,576 pixel-pairs

    fdl_kernel<<<NBLK, NTHR>>>(logits, target, cw, fa, out, P2);
}